// round 1
// baseline (speedup 1.0000x reference)
#include <cuda_runtime.h>
#include <math.h>

#define N_TOK 8192
#define DIM   1024
#define HID   4096
#define NE    8
#define TOPK  2

#define BM 128
#define BN 128
#define BK 8

// ---------------- device scratch (no allocations allowed) ----------------
__device__ int   g_count[NE];
__device__ int   g_off[NE];
__device__ int   g_tok[NE * N_TOK];
__device__ float g_gate[NE * N_TOK];
__device__ float g_h[(size_t)N_TOK * TOPK * HID];   // 16384 x 4096 f32 = 268 MB
__device__ float g_ent;
__device__ float g_imp[NE];

// ---------------- init ----------------
__global__ void zero_kernel() {
    int t = threadIdx.x;
    if (t < NE) { g_count[t] = 0; g_imp[t] = 0.f; }
    if (t == 0) g_ent = 0.f;
}

// ---------------- router: logits, softmax stats, top-2 scatter ----------------
__global__ void router_kernel(const float* __restrict__ x,
                              const float* __restrict__ rw,
                              const float* __restrict__ rb) {
    __shared__ float s_ent[8];
    __shared__ float s_imp[8][NE];
    int warp = threadIdx.x >> 5;
    int lane = threadIdx.x & 31;
    int t = blockIdx.x * 8 + warp;

    float acc[NE];
#pragma unroll
    for (int e = 0; e < NE; e++) acc[e] = 0.f;

    const float* xr = x + (size_t)t * DIM;
    for (int k = lane; k < DIM; k += 32) {
        float xv = xr[k];
        const float* rwk = rw + k * NE;
#pragma unroll
        for (int e = 0; e < NE; e++) acc[e] += xv * rwk[e];
    }
#pragma unroll
    for (int e = 0; e < NE; e++) {
#pragma unroll
        for (int s = 16; s > 0; s >>= 1)
            acc[e] += __shfl_xor_sync(0xffffffff, acc[e], s);
    }

    if (lane == 0) {
        float lg[NE];
        float m = -1e30f;
#pragma unroll
        for (int e = 0; e < NE; e++) { lg[e] = acc[e] + rb[e]; m = fmaxf(m, lg[e]); }
        float p[NE], sum = 0.f;
#pragma unroll
        for (int e = 0; e < NE; e++) { p[e] = expf(lg[e] - m); sum += p[e]; }
        float inv = 1.f / sum;
        float ent = 0.f;
#pragma unroll
        for (int e = 0; e < NE; e++) {
            float pe = p[e] * inv;
            ent -= pe * logf(fmaxf(pe, 1e-8f));
            s_imp[warp][e] = pe;
        }
        s_ent[warp] = ent;

        // top-2 (strict >, lowest index wins ties, matching jax top_k)
        int e0 = 0;
#pragma unroll
        for (int e = 1; e < NE; e++) if (lg[e] > lg[e0]) e0 = e;
        int e1 = (e0 == 0) ? 1 : 0;
#pragma unroll
        for (int e = 0; e < NE; e++) if (e != e0 && lg[e] > lg[e1]) e1 = e;

        float g0 = 1.f / (1.f + expf(lg[e1] - lg[e0]));
        float g1 = 1.f - g0;

        int p0 = atomicAdd(&g_count[e0], 1);
        g_tok [e0 * N_TOK + p0] = t;
        g_gate[e0 * N_TOK + p0] = g0;
        int p1 = atomicAdd(&g_count[e1], 1);
        g_tok [e1 * N_TOK + p1] = t;
        g_gate[e1 * N_TOK + p1] = g1;
    }
    __syncthreads();
    if (threadIdx.x < NE) {
        float se = 0.f;
#pragma unroll
        for (int w = 0; w < 8; w++) se += s_imp[w][threadIdx.x];
        atomicAdd(&g_imp[threadIdx.x], se);
    }
    if (threadIdx.x == 0) {
        float se = 0.f;
#pragma unroll
        for (int w = 0; w < 8; w++) se += s_ent[w];
        atomicAdd(&g_ent, se);
    }
}

__global__ void offsets_kernel() {
    if (threadIdx.x == 0) {
        int s = 0;
#pragma unroll
        for (int e = 0; e < NE; e++) { g_off[e] = s; s += g_count[e]; }
    }
}

// ---------------- SGEMM1: h = relu(X_gathered @ w1[e] + b1[e]) ----------------
__global__ void __launch_bounds__(256, 2)
gemm1_kernel(const float* __restrict__ x,
             const float* __restrict__ w1,
             const float* __restrict__ b1) {
    int e = blockIdx.z;
    int ce = g_count[e];
    int m0 = blockIdx.y * BM;
    if (m0 >= ce) return;
    int n0 = blockIdx.x * BN;
    int off = g_off[e];

    __shared__ float As[BK][BM + 4];
    __shared__ float Bs[BK][BN + 4];

    int tid = threadIdx.x;
    int am = tid >> 1, ak = (tid & 1) * 4;
    int bkr = tid >> 5, bn = (tid & 31) * 4;
    int tx = tid & 15, ty = tid >> 4;

    int tok_am = (m0 + am < ce) ? g_tok[e * N_TOK + m0 + am] : -1;
    const float* Ag = (tok_am >= 0) ? (x + (size_t)tok_am * DIM + ak) : x;
    const float* Bg = w1 + (size_t)e * DIM * HID + (size_t)bkr * HID + n0 + bn;

    float acc[8][8];
#pragma unroll
    for (int i = 0; i < 8; i++)
#pragma unroll
        for (int j = 0; j < 8; j++) acc[i][j] = 0.f;

    for (int k0 = 0; k0 < DIM; k0 += BK) {
        float4 av = make_float4(0.f, 0.f, 0.f, 0.f);
        if (tok_am >= 0) av = *(const float4*)(Ag + k0);
        As[ak + 0][am] = av.x; As[ak + 1][am] = av.y;
        As[ak + 2][am] = av.z; As[ak + 3][am] = av.w;
        *(float4*)&Bs[bkr][bn] = *(const float4*)(Bg + (size_t)k0 * HID);
        __syncthreads();
#pragma unroll
        for (int kk = 0; kk < BK; kk++) {
            float a[8], b[8];
            *(float4*)&a[0] = *(const float4*)&As[kk][ty * 4];
            *(float4*)&a[4] = *(const float4*)&As[kk][ty * 4 + 64];
            *(float4*)&b[0] = *(const float4*)&Bs[kk][tx * 4];
            *(float4*)&b[4] = *(const float4*)&Bs[kk][tx * 4 + 64];
#pragma unroll
            for (int i = 0; i < 8; i++)
#pragma unroll
                for (int j = 0; j < 8; j++)
                    acc[i][j] += a[i] * b[j];
        }
        __syncthreads();
    }

    float4 bv0 = *(const float4*)&b1[e * HID + n0 + tx * 4];
    float4 bv1 = *(const float4*)&b1[e * HID + n0 + tx * 4 + 64];
#pragma unroll
    for (int i = 0; i < 8; i++) {
        int m = (i < 4) ? (ty * 4 + i) : (64 + ty * 4 + i - 4);
        if (m0 + m < ce) {
            size_t base = (size_t)(off + m0 + m) * HID + n0;
            float4 o0, o1;
            o0.x = fmaxf(acc[i][0] + bv0.x, 0.f);
            o0.y = fmaxf(acc[i][1] + bv0.y, 0.f);
            o0.z = fmaxf(acc[i][2] + bv0.z, 0.f);
            o0.w = fmaxf(acc[i][3] + bv0.w, 0.f);
            o1.x = fmaxf(acc[i][4] + bv1.x, 0.f);
            o1.y = fmaxf(acc[i][5] + bv1.y, 0.f);
            o1.z = fmaxf(acc[i][6] + bv1.z, 0.f);
            o1.w = fmaxf(acc[i][7] + bv1.w, 0.f);
            *(float4*)&g_h[base + tx * 4]      = o0;
            *(float4*)&g_h[base + tx * 4 + 64] = o1;
        }
    }
}

// ---------------- SGEMM2: out[tok] += g * (h @ w2[e] + b2[e]) ----------------
__global__ void __launch_bounds__(256, 2)
gemm2_kernel(const float* __restrict__ w2,
             const float* __restrict__ b2,
             float* __restrict__ out) {
    int e = blockIdx.z;
    int ce = g_count[e];
    int m0 = blockIdx.y * BM;
    if (m0 >= ce) return;
    int n0 = blockIdx.x * BN;
    int off = g_off[e];

    __shared__ float As[BK][BM + 4];
    __shared__ float Bs[BK][BN + 4];

    int tid = threadIdx.x;
    int am = tid >> 1, ak = (tid & 1) * 4;
    int bkr = tid >> 5, bn = (tid & 31) * 4;
    int tx = tid & 15, ty = tid >> 4;

    bool mvalid = (m0 + am < ce);
    const float* Ag = g_h + (size_t)(off + m0 + (mvalid ? am : 0)) * HID + ak;
    const float* Bg = w2 + (size_t)e * HID * DIM + (size_t)bkr * DIM + n0 + bn;

    float acc[8][8];
#pragma unroll
    for (int i = 0; i < 8; i++)
#pragma unroll
        for (int j = 0; j < 8; j++) acc[i][j] = 0.f;

    for (int k0 = 0; k0 < HID; k0 += BK) {
        float4 av = make_float4(0.f, 0.f, 0.f, 0.f);
        if (mvalid) av = *(const float4*)(Ag + k0);
        As[ak + 0][am] = av.x; As[ak + 1][am] = av.y;
        As[ak + 2][am] = av.z; As[ak + 3][am] = av.w;
        *(float4*)&Bs[bkr][bn] = *(const float4*)(Bg + (size_t)k0 * DIM);
        __syncthreads();
#pragma unroll
        for (int kk = 0; kk < BK; kk++) {
            float a[8], b[8];
            *(float4*)&a[0] = *(const float4*)&As[kk][ty * 4];
            *(float4*)&a[4] = *(const float4*)&As[kk][ty * 4 + 64];
            *(float4*)&b[0] = *(const float4*)&Bs[kk][tx * 4];
            *(float4*)&b[4] = *(const float4*)&Bs[kk][tx * 4 + 64];
#pragma unroll
            for (int i = 0; i < 8; i++)
#pragma unroll
                for (int j = 0; j < 8; j++)
                    acc[i][j] += a[i] * b[j];
        }
        __syncthreads();
    }

    float4 bv0 = *(const float4*)&b2[e * DIM + n0 + tx * 4];
    float4 bv1 = *(const float4*)&b2[e * DIM + n0 + tx * 4 + 64];
#pragma unroll
    for (int i = 0; i < 8; i++) {
        int m = (i < 4) ? (ty * 4 + i) : (64 + ty * 4 + i - 4);
        if (m0 + m < ce) {
            int slot = e * N_TOK + m0 + m;
            int tok = g_tok[slot];
            float g = g_gate[slot];
            float* ob = out + (size_t)tok * DIM + n0;
            atomicAdd(&ob[tx * 4 + 0],      g * (acc[i][0] + bv0.x));
            atomicAdd(&ob[tx * 4 + 1],      g * (acc[i][1] + bv0.y));
            atomicAdd(&ob[tx * 4 + 2],      g * (acc[i][2] + bv0.z));
            atomicAdd(&ob[tx * 4 + 3],      g * (acc[i][3] + bv0.w));
            atomicAdd(&ob[tx * 4 + 64],     g * (acc[i][4] + bv1.x));
            atomicAdd(&ob[tx * 4 + 65],     g * (acc[i][5] + bv1.y));
            atomicAdd(&ob[tx * 4 + 66],     g * (acc[i][6] + bv1.z));
            atomicAdd(&ob[tx * 4 + 67],     g * (acc[i][7] + bv1.w));
        }
    }
}

// ---------------- aux losses ----------------
__global__ void aux_kernel(float* __restrict__ out, int out_size) {
    if (threadIdx.x == 0 && out_size >= N_TOK * DIM + 2) {
        float ent = g_ent / (float)N_TOK;
        float lb = 0.f;
#pragma unroll
        for (int e = 0; e < NE; e++) {
            float d = g_imp[e] / (float)N_TOK - 1.f / (float)NE;
            lb += d * d;
        }
        lb /= (float)NE;
        out[N_TOK * DIM]     = ent;
        out[N_TOK * DIM + 1] = lb;
    }
}

// ---------------- launch ----------------
extern "C" void kernel_launch(void* const* d_in, const int* in_sizes, int n_in,
                              void* d_out, int out_size) {
    const float* x  = (const float*)d_in[0];
    const float* rw = (const float*)d_in[1];
    const float* rb = (const float*)d_in[2];
    const float* w1 = (const float*)d_in[3];
    const float* b1 = (const float*)d_in[4];
    const float* w2 = (const float*)d_in[5];
    const float* b2 = (const float*)d_in[6];
    float* out = (float*)d_out;

    cudaMemsetAsync(d_out, 0, (size_t)out_size * sizeof(float), 0);
    zero_kernel<<<1, 32>>>();
    router_kernel<<<N_TOK / 8, 256>>>(x, rw, rb);
    offsets_kernel<<<1, 1>>>();

    dim3 g1(HID / BN, N_TOK / BM, NE);
    gemm1_kernel<<<g1, 256>>>(x, w1, b1);

    dim3 g2(DIM / BN, N_TOK / BM, NE);
    gemm2_kernel<<<g2, 256>>>(w2, b2, out);

    aux_kernel<<<1, 1>>>(out, out_size);
}

// round 6
// speedup vs baseline: 1.8100x; 1.8100x over previous
#include <cuda_runtime.h>
#include <cuda_bf16.h>
#include <math.h>
#include <stdint.h>

#define N_TOK 8192
#define DIM   1024
#define HID   4096
#define NE    8
#define STRD  12

// ======================= PTX helpers =======================
__device__ __forceinline__ void mma_bf16(float* d, const uint32_t* a, const uint32_t* b) {
    asm volatile("mma.sync.aligned.m16n8k16.row.col.f32.bf16.bf16.f32 "
                 "{%0,%1,%2,%3},{%4,%5,%6,%7},{%8,%9},{%0,%1,%2,%3};"
                 : "+f"(d[0]), "+f"(d[1]), "+f"(d[2]), "+f"(d[3])
                 : "r"(a[0]), "r"(a[1]), "r"(a[2]), "r"(a[3]), "r"(b[0]), "r"(b[1]));
}

// ======================= device scratch =======================
__device__ int   g_count[NE];
__device__ int   g_off[NE];
__device__ int   g_tok[NE * N_TOK];
__device__ float g_gate[NE * N_TOK];
__device__ float g_ent;
__device__ float g_imp[NE];

__device__ __align__(16) __nv_bfloat16 g_xh[(size_t)N_TOK * DIM];
__device__ __align__(16) __nv_bfloat16 g_xl[(size_t)N_TOK * DIM];
__device__ __align__(16) __nv_bfloat16 g_w1h[(size_t)NE * HID * DIM];   // [e][n(hid)][k(dim)]
__device__ __align__(16) __nv_bfloat16 g_w1l[(size_t)NE * HID * DIM];
__device__ __align__(16) __nv_bfloat16 g_w2h[(size_t)NE * DIM * HID];   // [e][n(dim)][k(hid)]
__device__ __align__(16) __nv_bfloat16 g_w2l[(size_t)NE * DIM * HID];
__device__ __align__(16) __nv_bfloat16 g_hh[(size_t)2 * N_TOK * HID];   // [slot][hid]
__device__ __align__(16) __nv_bfloat16 g_hl[(size_t)2 * N_TOK * HID];

// ======================= small kernels =======================
__global__ void zero_kernel() {
    int t = threadIdx.x;
    if (t < NE) { g_count[t] = 0; g_imp[t] = 0.f; }
    if (t == 0) g_ent = 0.f;
}

__global__ void router_kernel(const float* __restrict__ x,
                              const float* __restrict__ rw,
                              const float* __restrict__ rb) {
    __shared__ float s_ent[8];
    __shared__ float s_imp[8][NE];
    int warp = threadIdx.x >> 5;
    int lane = threadIdx.x & 31;
    int t = blockIdx.x * 8 + warp;

    float acc[NE];
#pragma unroll
    for (int e = 0; e < NE; e++) acc[e] = 0.f;
    const float* xr = x + (size_t)t * DIM;
    for (int k = lane; k < DIM; k += 32) {
        float xv = xr[k];
        const float* rwk = rw + k * NE;
#pragma unroll
        for (int e = 0; e < NE; e++) acc[e] += xv * rwk[e];
    }
#pragma unroll
    for (int e = 0; e < NE; e++)
#pragma unroll
        for (int s = 16; s > 0; s >>= 1)
            acc[e] += __shfl_xor_sync(0xffffffff, acc[e], s);

    if (lane == 0) {
        float lg[NE], m = -1e30f;
#pragma unroll
        for (int e = 0; e < NE; e++) { lg[e] = acc[e] + rb[e]; m = fmaxf(m, lg[e]); }
        float p[NE], sum = 0.f;
#pragma unroll
        for (int e = 0; e < NE; e++) { p[e] = expf(lg[e] - m); sum += p[e]; }
        float inv = 1.f / sum, ent = 0.f;
#pragma unroll
        for (int e = 0; e < NE; e++) {
            float pe = p[e] * inv;
            ent -= pe * logf(fmaxf(pe, 1e-8f));
            s_imp[warp][e] = pe;
        }
        s_ent[warp] = ent;
        int e0 = 0;
#pragma unroll
        for (int e = 1; e < NE; e++) if (lg[e] > lg[e0]) e0 = e;
        int e1 = (e0 == 0) ? 1 : 0;
#pragma unroll
        for (int e = 0; e < NE; e++) if (e != e0 && lg[e] > lg[e1]) e1 = e;
        float g0 = 1.f / (1.f + expf(lg[e1] - lg[e0]));
        float g1 = 1.f - g0;
        int p0 = atomicAdd(&g_count[e0], 1);
        g_tok [e0 * N_TOK + p0] = t; g_gate[e0 * N_TOK + p0] = g0;
        int p1 = atomicAdd(&g_count[e1], 1);
        g_tok [e1 * N_TOK + p1] = t; g_gate[e1 * N_TOK + p1] = g1;
    }
    __syncthreads();
    if (threadIdx.x < NE) {
        float se = 0.f;
#pragma unroll
        for (int w = 0; w < 8; w++) se += s_imp[w][threadIdx.x];
        atomicAdd(&g_imp[threadIdx.x], se);
    }
    if (threadIdx.x == 0) {
        float se = 0.f;
#pragma unroll
        for (int w = 0; w < 8; w++) se += s_ent[w];
        atomicAdd(&g_ent, se);
    }
}

__global__ void offsets_kernel() {
    if (threadIdx.x == 0) {
        int s = 0;
#pragma unroll
        for (int e = 0; e < NE; e++) { g_off[e] = s; s += g_count[e]; }
    }
}

__global__ void convert_x_kernel(const float* __restrict__ x) {
    size_t i = ((size_t)blockIdx.x * 256 + threadIdx.x) * 4;
    float4 v = *(const float4*)(x + i);
    float f[4] = {v.x, v.y, v.z, v.w};
    uint32_t ph[2], pl[2];
#pragma unroll
    for (int j = 0; j < 2; j++) {
        __nv_bfloat16 h0 = __float2bfloat16(f[2*j]),   h1 = __float2bfloat16(f[2*j+1]);
        __nv_bfloat16 l0 = __float2bfloat16(f[2*j]   - __bfloat162float(h0));
        __nv_bfloat16 l1 = __float2bfloat16(f[2*j+1] - __bfloat162float(h1));
        ph[j] = (uint32_t)__bfloat16_as_ushort(h0) | ((uint32_t)__bfloat16_as_ushort(h1) << 16);
        pl[j] = (uint32_t)__bfloat16_as_ushort(l0) | ((uint32_t)__bfloat16_as_ushort(l1) << 16);
    }
    *(uint2*)(g_xh + i) = make_uint2(ph[0], ph[1]);
    *(uint2*)(g_xl + i) = make_uint2(pl[0], pl[1]);
}

// transpose+split: src [e][R][C] fp32 -> INTERNAL dst [e][C][R] bf16 hi/lo
// which=0 -> g_w1h/g_w1l ; which=1 -> g_w2h/g_w2l
// (device globals must NOT be passed as kernel args from host — host shadow
//  symbol != device address; that bug zeroed rounds 3-5.)
__global__ void transpose_convert_kernel(const float* __restrict__ src,
                                         int which, int R, int C) {
    __shared__ float t[32][33];
    __nv_bfloat16* dh = which ? g_w2h : g_w1h;
    __nv_bfloat16* dl = which ? g_w2l : g_w1l;
    int e = blockIdx.z;
    int c0 = blockIdx.x * 32, r0 = blockIdx.y * 32;
    const float* s = src + (size_t)e * R * C;
#pragma unroll
    for (int i = threadIdx.y; i < 32; i += 8)
        t[i][threadIdx.x] = s[(size_t)(r0 + i) * C + c0 + threadIdx.x];
    __syncthreads();
#pragma unroll
    for (int i = threadIdx.y; i < 32; i += 8) {
        float v = t[threadIdx.x][i];
        __nv_bfloat16 h = __float2bfloat16(v);
        __nv_bfloat16 l = __float2bfloat16(v - __bfloat162float(h));
        size_t o = (size_t)e * R * C + (size_t)(c0 + i) * R + r0 + threadIdx.x;
        dh[o] = h; dl[o] = l;
    }
}

// ======================= GEMM mainloop (HMMA, 3-term bf16 split) =======================
__device__ __forceinline__ void mma_mainloop(
    uint32_t (*smA)[128][STRD], uint32_t (*smB)[128][STRD],
    const __nv_bfloat16* __restrict__ Ah, const __nv_bfloat16* __restrict__ Al,
    const __nv_bfloat16* __restrict__ Bh, const __nv_bfloat16* __restrict__ Bl,
    const uint32_t* __restrict__ arow, const uint32_t* __restrict__ brow,
    int S, float (&acc)[4][4][4])
{
    int tid  = threadIdx.x;
    int lane = tid & 31;
    int wid  = tid >> 5;
    int wm   = wid & 1;        // 2 m-groups of 64
    int wn   = wid >> 1;       // 4 n-groups of 32
    int q    = lane & 3;
    int r4   = lane >> 2;

    int lrow  = tid >> 1;      // 0..127
    int lhalf = tid & 1;       // which 8-elem half of k16
    uint32_t ar = arow[lrow];
    uint32_t br = brow[lrow];

    // prefetch stage 0 into registers
    uint4 vah = *(const uint4*)(Ah + ar + lhalf * 8);
    uint4 val = *(const uint4*)(Al + ar + lhalf * 8);
    uint4 vbh = *(const uint4*)(Bh + br + lhalf * 8);
    uint4 vbl = *(const uint4*)(Bl + br + lhalf * 8);

    for (int s = 0; s < S; s++) {
        __syncthreads();   // previous stage fully consumed
        *(uint4*)&smA[0][lrow][lhalf * 4] = vah;
        *(uint4*)&smA[1][lrow][lhalf * 4] = val;
        *(uint4*)&smB[0][lrow][lhalf * 4] = vbh;
        *(uint4*)&smB[1][lrow][lhalf * 4] = vbl;
        __syncthreads();   // stage visible
        if (s + 1 < S) {
            int k0 = (s + 1) * 16 + lhalf * 8;
            vah = *(const uint4*)(Ah + ar + k0);
            val = *(const uint4*)(Al + ar + k0);
            vbh = *(const uint4*)(Bh + br + k0);
            vbl = *(const uint4*)(Bl + br + k0);
        }
        // B fragments: b0 = B[n][k pair q], b1 = B[n][k pair q+4]
        uint32_t bh[4][2], bl[4][2];
#pragma unroll
        for (int nt = 0; nt < 4; nt++) {
            int nb = wn * 32 + nt * 8 + r4;
            bh[nt][0] = smB[0][nb][q];     bh[nt][1] = smB[0][nb][4 + q];
            bl[nt][0] = smB[1][nb][q];     bl[nt][1] = smB[1][nb][4 + q];
        }
#pragma unroll
        for (int mt = 0; mt < 4; mt++) {
            int ra = wm * 64 + mt * 16 + r4;
            uint32_t ah[4], al[4];
            ah[0] = smA[0][ra][q];      ah[1] = smA[0][ra + 8][q];
            ah[2] = smA[0][ra][4 + q];  ah[3] = smA[0][ra + 8][4 + q];
            al[0] = smA[1][ra][q];      al[1] = smA[1][ra + 8][q];
            al[2] = smA[1][ra][4 + q];  al[3] = smA[1][ra + 8][4 + q];
#pragma unroll
            for (int nt = 0; nt < 4; nt++) {
                mma_bf16(acc[mt][nt], ah, bh[nt]);
                mma_bf16(acc[mt][nt], al, bh[nt]);
                mma_bf16(acc[mt][nt], ah, bl[nt]);
            }
        }
    }
}

// ======================= GEMM1: h = relu(x @ w1 + b1) =======================
__global__ void __launch_bounds__(256)
gemm1_mma(const float* __restrict__ b1) {
    int e = blockIdx.z;
    int ce = g_count[e];
    int m0 = blockIdx.y * 128;
    if (m0 >= ce) return;
    int n0 = blockIdx.x * 128;
    int off = g_off[e];

    __shared__ __align__(16) uint32_t smA[2][128][STRD];
    __shared__ __align__(16) uint32_t smB[2][128][STRD];
    __shared__ uint32_t s_arow[128];
    __shared__ uint32_t s_brow[128];

    int tid = threadIdx.x;
    if (tid < 128) {
        int tok = (m0 + tid < ce) ? g_tok[e * N_TOK + m0 + tid] : 0;
        s_arow[tid] = (uint32_t)tok * DIM;
        s_brow[tid] = (uint32_t)(e * HID + n0 + tid) * DIM;
    }
    __syncthreads();

    float acc[4][4][4];
#pragma unroll
    for (int i = 0; i < 4; i++)
#pragma unroll
        for (int j = 0; j < 4; j++)
#pragma unroll
            for (int k = 0; k < 4; k++) acc[i][j][k] = 0.f;

    mma_mainloop(smA, smB, g_xh, g_xl, g_w1h, g_w1l, s_arow, s_brow, DIM / 16, acc);

    // epilogue: bias + relu + split -> g_hh / g_hl
    int lane = tid & 31, wid = tid >> 5;
    int wm = wid & 1, wn = wid >> 1;
    int r = lane >> 2, q = lane & 3;
#pragma unroll
    for (int mt = 0; mt < 4; mt++) {
#pragma unroll
        for (int rh = 0; rh < 2; rh++) {
            int row = wm * 64 + mt * 16 + r + rh * 8;
            if (m0 + row >= ce) continue;
            size_t slot = (size_t)(off + m0 + row);
#pragma unroll
            for (int nt = 0; nt < 4; nt++) {
                int col = n0 + wn * 32 + nt * 8 + 2 * q;
                float f0 = acc[mt][nt][rh * 2 + 0] + b1[e * HID + col];
                float f1 = acc[mt][nt][rh * 2 + 1] + b1[e * HID + col + 1];
                f0 = fmaxf(f0, 0.f); f1 = fmaxf(f1, 0.f);
                __nv_bfloat16 h0 = __float2bfloat16(f0), h1 = __float2bfloat16(f1);
                __nv_bfloat16 l0 = __float2bfloat16(f0 - __bfloat162float(h0));
                __nv_bfloat16 l1 = __float2bfloat16(f1 - __bfloat162float(h1));
                uint32_t ph = (uint32_t)__bfloat16_as_ushort(h0) | ((uint32_t)__bfloat16_as_ushort(h1) << 16);
                uint32_t pl = (uint32_t)__bfloat16_as_ushort(l0) | ((uint32_t)__bfloat16_as_ushort(l1) << 16);
                *(uint32_t*)(g_hh + slot * HID + col) = ph;
                *(uint32_t*)(g_hl + slot * HID + col) = pl;
            }
        }
    }
}

// ======================= GEMM2: out += gate * (h @ w2 + b2) =======================
__global__ void __launch_bounds__(256)
gemm2_mma(const float* __restrict__ b2, float* __restrict__ out) {
    int e = blockIdx.z;
    int ce = g_count[e];
    int m0 = blockIdx.y * 128;
    if (m0 >= ce) return;
    int n0 = blockIdx.x * 128;
    int off = g_off[e];

    __shared__ __align__(16) uint32_t smA[2][128][STRD];
    __shared__ __align__(16) uint32_t smB[2][128][STRD];
    __shared__ uint32_t s_arow[128];
    __shared__ uint32_t s_brow[128];

    int tid = threadIdx.x;
    if (tid < 128) {
        int sl = off + m0 + tid;
        if (sl > 2 * N_TOK - 1) sl = 2 * N_TOK - 1;
        s_arow[tid] = (uint32_t)sl * HID;
        s_brow[tid] = (uint32_t)(e * DIM + n0 + tid) * HID;
    }
    __syncthreads();

    float acc[4][4][4];
#pragma unroll
    for (int i = 0; i < 4; i++)
#pragma unroll
        for (int j = 0; j < 4; j++)
#pragma unroll
            for (int k = 0; k < 4; k++) acc[i][j][k] = 0.f;

    mma_mainloop(smA, smB, g_hh, g_hl, g_w2h, g_w2l, s_arow, s_brow, HID / 16, acc);

    // epilogue: gate-weighted atomic add
    int lane = tid & 31, wid = tid >> 5;
    int wm = wid & 1, wn = wid >> 1;
    int r = lane >> 2, q = lane & 3;
#pragma unroll
    for (int mt = 0; mt < 4; mt++) {
#pragma unroll
        for (int rh = 0; rh < 2; rh++) {
            int row = wm * 64 + mt * 16 + r + rh * 8;
            if (m0 + row >= ce) continue;
            int slot2 = e * N_TOK + m0 + row;
            int tok = g_tok[slot2];
            float gw = g_gate[slot2];
            float* ob = out + (size_t)tok * DIM;
#pragma unroll
            for (int nt = 0; nt < 4; nt++) {
                int col = n0 + wn * 32 + nt * 8 + 2 * q;
                float f0 = acc[mt][nt][rh * 2 + 0] + b2[e * DIM + col];
                float f1 = acc[mt][nt][rh * 2 + 1] + b2[e * DIM + col + 1];
                atomicAdd(ob + col,     gw * f0);
                atomicAdd(ob + col + 1, gw * f1);
            }
        }
    }
}

// ======================= aux =======================
__global__ void aux_kernel(float* __restrict__ out, int out_size) {
    if (threadIdx.x == 0 && out_size >= N_TOK * DIM + 2) {
        float ent = g_ent / (float)N_TOK;
        float lb = 0.f;
#pragma unroll
        for (int e = 0; e < NE; e++) {
            float d = g_imp[e] / (float)N_TOK - 1.f / (float)NE;
            lb += d * d;
        }
        lb /= (float)NE;
        out[N_TOK * DIM]     = ent;
        out[N_TOK * DIM + 1] = lb;
    }
}

// ======================= launch =======================
extern "C" void kernel_launch(void* const* d_in, const int* in_sizes, int n_in,
                              void* d_out, int out_size) {
    const float* x  = (const float*)d_in[0];
    const float* rw = (const float*)d_in[1];
    const float* rb = (const float*)d_in[2];
    const float* w1 = (const float*)d_in[3];
    const float* b1 = (const float*)d_in[4];
    const float* w2 = (const float*)d_in[5];
    const float* b2 = (const float*)d_in[6];
    float* out = (float*)d_out;

    cudaMemsetAsync(d_out, 0, (size_t)out_size * sizeof(float), 0);
    zero_kernel<<<1, 32>>>();
    router_kernel<<<N_TOK / 8, 256>>>(x, rw, rb);
    offsets_kernel<<<1, 1>>>();

    convert_x_kernel<<<(N_TOK * DIM) / 1024, 256>>>(x);
    {
        dim3 g(HID / 32, DIM / 32, NE), b(32, 8);
        transpose_convert_kernel<<<g, b>>>(w1, 0, DIM, HID);
    }
    {
        dim3 g(DIM / 32, HID / 32, NE), b(32, 8);
        transpose_convert_kernel<<<g, b>>>(w2, 1, HID, DIM);
    }

    {
        dim3 g(HID / 128, N_TOK / 128, NE);
        gemm1_mma<<<g, 256>>>(b1);
    }
    {
        dim3 g(DIM / 128, N_TOK / 128, NE);
        gemm2_mma<<<g, 256>>>(b2, out);
    }
    aux_kernel<<<1, 1>>>(out, out_size);
}